// round 7
// baseline (speedup 1.0000x reference)
#include <cuda_runtime.h>
#include <cuda_bf16.h>
#include <math.h>

// Problem constants
#define NMAX   50000
#define EMAX   600000
#define FIN    74
#define KIN    80          // FIN padded to multiple of 16
#define HDIM   128
#define NG     500

// ---------------- scratch (device globals) ----------------
__device__ __align__(16) float g_h[NMAX * HDIM];            // node features fp32
__device__ __align__(16) __nv_bfloat16 g_ahi[NMAX * HDIM];  // GEMM A operand hi
__device__ __align__(16) __nv_bfloat16 g_alo[NMAX * HDIM];  // GEMM A operand lo
__device__ __align__(16) __nv_bfloat16 g_xhi[NMAX * KIN];   // padded x hi
__device__ __align__(16) __nv_bfloat16 g_xlo[NMAX * KIN];   // padded x lo
// transposed weights: Wt[n][k].  in: 128*80, g0/g1/g2: 128*128 each
#define WT_IN_OFF  0
#define WT_G_OFF   (128*KIN)
#define WT_TOTAL   (128*KIN + 3*128*128)
__device__ __align__(16) __nv_bfloat16 g_wthi[WT_TOTAL];
__device__ __align__(16) __nv_bfloat16 g_wtlo[WT_TOTAL];

__device__ int   g_outcnt[NMAX];
__device__ int   g_incnt[NMAX];
__device__ int   g_rowptr[NMAX + 1];
__device__ int   g_fill[NMAX];
__device__ int   g_col[EMAX];
__device__ float g_outnorm[NMAX];
__device__ float g_innorm[NMAX];
__device__ __align__(16) float g_pooled[NG * HDIM];
__device__ int   g_gcnt[NG];

// ---------------- init ----------------
__global__ void k_init(int N) {
    int i = blockIdx.x * blockDim.x + threadIdx.x;
    if (i < N) { g_outcnt[i] = 0; g_incnt[i] = 0; }
    if (i < NG * HDIM) g_pooled[i] = 0.0f;
    if (i < NG) g_gcnt[i] = 0;
}

// ---------------- degree histogram ----------------
__global__ void k_hist(const int* __restrict__ src, const int* __restrict__ dst, int E) {
    int i = blockIdx.x * blockDim.x + threadIdx.x;
    if (i < E) {
        atomicAdd(&g_outcnt[src[i]], 1);
        atomicAdd(&g_incnt[dst[i]], 1);
    }
}

// ---------------- single-block scan: rowptr + norms ----------------
__global__ void k_scan(int N) {
    __shared__ int sh[1024];
    int t = threadIdx.x;
    int CH = (N + 1023) >> 10;
    int a0 = t * CH;
    int a1 = a0 + CH; if (a1 > N) a1 = N;
    int s = 0;
    for (int i = a0; i < a1; ++i) s += g_incnt[i];
    sh[t] = s;
    __syncthreads();
    for (int off = 1; off < 1024; off <<= 1) {
        int v = (t >= off) ? sh[t - off] : 0;
        __syncthreads();
        sh[t] += v;
        __syncthreads();
    }
    int base = sh[t] - s;
    for (int i = a0; i < a1; ++i) {
        int c = g_incnt[i];
        g_rowptr[i] = base;
        g_fill[i]   = base;
        base += c;
        g_innorm[i]  = rsqrtf((float)(c > 0 ? c : 1));
        int oc = g_outcnt[i];
        g_outnorm[i] = rsqrtf((float)(oc > 0 ? oc : 1));
    }
    if (t == 1023) g_rowptr[N] = sh[1023];
}

// ---------------- CSR placement ----------------
__global__ void k_fill(const int* __restrict__ src, const int* __restrict__ dst, int E) {
    int i = blockIdx.x * blockDim.x + threadIdx.x;
    if (i < E) {
        int d = dst[i];
        int p = atomicAdd(&g_fill[d], 1);
        g_col[p] = src[i];
    }
}

// ---------------- hi/lo split helpers ----------------
__device__ __forceinline__ void split_bf(float v, __nv_bfloat16& hi, __nv_bfloat16& lo) {
    hi = __float2bfloat16_rn(v);
    lo = __float2bfloat16_rn(v - __bfloat162float(hi));
}

// ---------------- fused prep: pad+split x, transpose+split weights ---------
__global__ void k_prep(const float* __restrict__ x,
                       const float* __restrict__ Win,
                       const float* __restrict__ Wg0,
                       const float* __restrict__ Wg1,
                       const float* __restrict__ Wg2, int N) {
    int i = blockIdx.x * blockDim.x + threadIdx.x;
    int nx = N * KIN;
    if (i < nx) {
        int r = i / KIN, k = i - r * KIN;
        float v = (k < FIN) ? x[r * FIN + k] : 0.0f;
        split_bf(v, g_xhi[i], g_xlo[i]);
        return;
    }
    i -= nx;
    if (i < 128 * KIN) {
        int n = i / KIN, k = i % KIN;
        float v = (k < FIN) ? Win[k * 128 + n] : 0.0f;
        split_bf(v, g_wthi[WT_IN_OFF + i], g_wtlo[WT_IN_OFF + i]);
    } else if (i < 128 * KIN + 3 * 128 * 128) {
        int j = i - 128 * KIN;
        int l = j / (128 * 128);
        int r = j - l * 128 * 128;
        int n = r / 128, k = r % 128;
        const float* W = (l == 0) ? Wg0 : (l == 1) ? Wg1 : Wg2;
        float v = W[k * 128 + n];
        split_bf(v, g_wthi[WT_G_OFF + j], g_wtlo[WT_G_OFF + j]);
    }
}

// ---------------- tensor-core GEMM + bias + SiLU ----------------
// out[N,128] = silu(A[N,KP] @ W[KP,128] + b), A/W split hi+lo bf16.
// Block: 256 thr (8 warps = 4M x 2N), tile 128 rows x 128 cols.
// Warp tile: 32 rows (two m16) x 64 cols (eight n8).
__device__ __forceinline__ float silu1(float v) { return v / (1.0f + __expf(-v)); }

__device__ __forceinline__ void mma16816(float* d, const unsigned* a, const unsigned* b) {
    asm volatile(
        "mma.sync.aligned.m16n8k16.row.col.f32.bf16.bf16.f32 "
        "{%0,%1,%2,%3}, {%4,%5,%6,%7}, {%8,%9}, {%0,%1,%2,%3};"
        : "+f"(d[0]), "+f"(d[1]), "+f"(d[2]), "+f"(d[3])
        : "r"(a[0]), "r"(a[1]), "r"(a[2]), "r"(a[3]), "r"(b[0]), "r"(b[1]));
}

__device__ __forceinline__ void ldsm4(unsigned* r, unsigned addr) {
    asm volatile("ldmatrix.sync.aligned.m8n8.x4.shared.b16 {%0,%1,%2,%3}, [%4];"
                 : "=r"(r[0]), "=r"(r[1]), "=r"(r[2]), "=r"(r[3]) : "r"(addr));
}

template <int KP>
__global__ void __launch_bounds__(256)
k_gemm_tc(const __nv_bfloat16* __restrict__ Ahi, const __nv_bfloat16* __restrict__ Alo,
          const __nv_bfloat16* __restrict__ Whi, const __nv_bfloat16* __restrict__ Wlo,
          const float* __restrict__ bias, float* __restrict__ out, int N) {
    constexpr int SW = KP / 2 + 4;             // padded row stride in 32-bit words
    constexpr int TW = 128 * SW;               // words per tile array
    extern __shared__ unsigned sh[];
    unsigned* sAh = sh;
    unsigned* sAl = sh + TW;
    unsigned* sWh = sh + 2 * TW;
    unsigned* sWl = sh + 3 * TW;

    const int tid  = threadIdx.x;
    const int lane = tid & 31;
    const int gid  = lane >> 2;
    const int tig  = lane & 3;
    const int warp = tid >> 5;
    const int wm   = warp & 3;        // M group (32 rows each)
    const int wn   = warp >> 2;       // N group (64 cols each)
    const int r0   = blockIdx.x * 128;

    // stage tiles: uint4 = 8 bf16 = 4 words
    constexpr int ACH = KP / 8;       // uint4 chunks per row
    for (int i = tid; i < 128 * ACH; i += 256) {
        int r = i / ACH, c = i - r * ACH;
        int gr = r0 + r;
        uint4 vh = make_uint4(0, 0, 0, 0), vl = vh;
        if (gr < N) {
            vh = reinterpret_cast<const uint4*>(Ahi + (size_t)gr * KP)[c];
            vl = reinterpret_cast<const uint4*>(Alo + (size_t)gr * KP)[c];
        }
        *reinterpret_cast<uint4*>(sAh + r * SW + c * 4) = vh;
        *reinterpret_cast<uint4*>(sAl + r * SW + c * 4) = vl;
        *reinterpret_cast<uint4*>(sWh + r * SW + c * 4) =
            reinterpret_cast<const uint4*>(Whi + (size_t)r * KP)[c];
        *reinterpret_cast<uint4*>(sWl + r * SW + c * 4) =
            reinterpret_cast<const uint4*>(Wlo + (size_t)r * KP)[c];
    }
    __syncthreads();

    // shared-space byte addresses for ldmatrix
    unsigned base_sh = (unsigned)__cvta_generic_to_shared(sh);
    // A: lane 0-15 -> rows m0..m0+15; lane>=16 -> +16B column offset
    int rowA = wm * 32 + (lane & 15);
    unsigned aoff = (unsigned)(rowA * SW) * 4u + ((lane >> 4) * 16u);
    // B: lanes {0-7,8-15,16-23,24-31} -> (n 0-7 k0),(n 0-7 k8),(n 8-15 k0),(n 8-15 k8)
    int rowB = wn * 64 + ((lane >> 4) << 3) + (lane & 7);
    unsigned boff = (unsigned)(rowB * SW) * 4u + (((lane >> 3) & 1) * 16u);

    unsigned aAh = base_sh + aoff;                    // into sAh
    unsigned aAl = base_sh + 4u * TW + aoff;          // into sAl (word offset TW)
    unsigned aWh = base_sh + 8u * TW + boff;
    unsigned aWl = base_sh + 12u * TW + boff;

    // accumulators: [mi][nt][4], init with bias
    float d[2][8][4];
#pragma unroll
    for (int nt = 0; nt < 8; ++nt) {
        int c = wn * 64 + nt * 8 + tig * 2;
        float b0 = bias[c], b1 = bias[c + 1];
#pragma unroll
        for (int mi = 0; mi < 2; ++mi) {
            d[mi][nt][0] = b0; d[mi][nt][1] = b1;
            d[mi][nt][2] = b0; d[mi][nt][3] = b1;
        }
    }

#pragma unroll
    for (int ks = 0; ks < KP / 16; ++ks) {
        unsigned kb = ks * 32u;  // 16 bf16 = 32 bytes
        unsigned ah[2][4], al[2][4];
#pragma unroll
        for (int mi = 0; mi < 2; ++mi) {
            unsigned mo = (unsigned)(mi * 16 * SW) * 4u + kb;
            ldsm4(ah[mi], aAh + mo);
            ldsm4(al[mi], aAl + mo);
        }
        unsigned bh[4][4], bl[4][4];
#pragma unroll
        for (int np = 0; np < 4; ++np) {
            unsigned no = (unsigned)(np * 16 * SW) * 4u + kb;
            ldsm4(bh[np], aWh + no);
            ldsm4(bl[np], aWl + no);
        }
#pragma unroll
        for (int nt = 0; nt < 8; ++nt) {
            const unsigned* bhp = &bh[nt >> 1][(nt & 1) * 2];
            const unsigned* blp = &bl[nt >> 1][(nt & 1) * 2];
#pragma unroll
            for (int mi = 0; mi < 2; ++mi) {
                mma16816(d[mi][nt], ah[mi], bhp);
                mma16816(d[mi][nt], ah[mi], blp);
                mma16816(d[mi][nt], al[mi], bhp);
            }
        }
    }

    // epilogue: silu + store fp32
#pragma unroll
    for (int mi = 0; mi < 2; ++mi) {
        int r1 = r0 + wm * 32 + mi * 16 + gid;
        int r2 = r1 + 8;
#pragma unroll
        for (int nt = 0; nt < 8; ++nt) {
            int c = wn * 64 + nt * 8 + tig * 2;
            if (r1 < N) {
                float2 v = make_float2(silu1(d[mi][nt][0]), silu1(d[mi][nt][1]));
                *reinterpret_cast<float2*>(out + (size_t)r1 * 128 + c) = v;
            }
            if (r2 < N) {
                float2 v = make_float2(silu1(d[mi][nt][2]), silu1(d[mi][nt][3]));
                *reinterpret_cast<float2*>(out + (size_t)r2 * 128 + c) = v;
            }
        }
    }
}

// ---------------- gather-aggregate -> bf16 hi/lo output ----------------
__global__ void k_agg(const float* __restrict__ h, int N) {
    int w = (blockIdx.x * blockDim.x + threadIdx.x) >> 5;
    int lane = threadIdx.x & 31;
    if (w >= N) return;
    int e0 = g_rowptr[w], e1 = g_rowptr[w + 1];
    const float4* h4 = reinterpret_cast<const float4*>(h);
    float4 acc = make_float4(0.f, 0.f, 0.f, 0.f);
    for (int e = e0; e < e1; ++e) {
        int s = g_col[e];
        float on = g_outnorm[s];
        float4 v = h4[s * 32 + lane];
        acc.x = fmaf(on, v.x, acc.x);
        acc.y = fmaf(on, v.y, acc.y);
        acc.z = fmaf(on, v.z, acc.z);
        acc.w = fmaf(on, v.w, acc.w);
    }
    float inn = g_innorm[w];
    float o[4] = {acc.x * inn, acc.y * inn, acc.z * inn, acc.w * inn};
    __nv_bfloat16 hi[4], lo[4];
#pragma unroll
    for (int j = 0; j < 4; ++j) split_bf(o[j], hi[j], lo[j]);
    size_t base = (size_t)w * 128 + lane * 4;
    *reinterpret_cast<__nv_bfloat162*>(g_ahi + base)     = __nv_bfloat162(hi[0], hi[1]);
    *reinterpret_cast<__nv_bfloat162*>(g_ahi + base + 2) = __nv_bfloat162(hi[2], hi[3]);
    *reinterpret_cast<__nv_bfloat162*>(g_alo + base)     = __nv_bfloat162(lo[0], lo[1]);
    *reinterpret_cast<__nv_bfloat162*>(g_alo + base + 2) = __nv_bfloat162(lo[2], lo[3]);
}

// ---------------- segment-sum pooling (graph_ids sorted) ----------------
__global__ void k_pool(const float* __restrict__ h, const int* __restrict__ gid, int N) {
    int r0 = blockIdx.x * 128;
    if (r0 >= N) return;
    int r1 = r0 + 128; if (r1 > N) r1 = N;
    int j = threadIdx.x;
    int cur = gid[r0];
    float acc = 0.0f;
    int run = 0;
    for (int r = r0; r < r1; ++r) {
        int g = gid[r];
        if (g != cur) {
            atomicAdd(&g_pooled[cur * HDIM + j], acc);
            if (j == 0) atomicAdd(&g_gcnt[cur], run);
            acc = 0.0f; run = 0; cur = g;
        }
        acc += h[(size_t)r * HDIM + j];
        ++run;
    }
    atomicAdd(&g_pooled[cur * HDIM + j], acc);
    if (j == 0) atomicAdd(&g_gcnt[cur], run);
}

// ---------------- final: (pooled @ W_out + cnt*b_out) @ W_ff + b_ff ----------
__global__ void k_final(const float* __restrict__ Wout, const float* __restrict__ bout,
                        const float* __restrict__ Wff, const float* __restrict__ bff,
                        float* __restrict__ out) {
    __shared__ float p[HDIM];
    __shared__ float red[HDIM];
    int g = blockIdx.x, j = threadIdx.x;
    p[j] = g_pooled[g * HDIM + j];
    __syncthreads();
    float t = (float)g_gcnt[g] * bout[j];
#pragma unroll 8
    for (int k = 0; k < HDIM; ++k)
        t = fmaf(p[k], Wout[k * HDIM + j], t);
    red[j] = t * Wff[j];
    __syncthreads();
    for (int s = 64; s > 0; s >>= 1) {
        if (j < s) red[j] += red[j + s];
        __syncthreads();
    }
    if (j == 0) out[g] = red[0] + bff[0];
}

// ---------------- launch ----------------
extern "C" void kernel_launch(void* const* d_in, const int* in_sizes, int n_in,
                              void* d_out, int out_size) {
    const float* x     = (const float*)d_in[0];
    const float* W_in  = (const float*)d_in[1];
    const float* b_in  = (const float*)d_in[2];
    const float* W_g0  = (const float*)d_in[3];
    const float* b_g0  = (const float*)d_in[4];
    const float* W_g1  = (const float*)d_in[5];
    const float* b_g1  = (const float*)d_in[6];
    const float* W_g2  = (const float*)d_in[7];
    const float* b_g2  = (const float*)d_in[8];
    const float* W_out = (const float*)d_in[9];
    const float* b_out = (const float*)d_in[10];
    const float* W_ff  = (const float*)d_in[11];
    const float* b_ff  = (const float*)d_in[12];
    const int*   src   = (const int*)d_in[13];
    const int*   dst   = (const int*)d_in[14];
    const int*   gids  = (const int*)d_in[15];
    float* out = (float*)d_out;

    const int N = in_sizes[0] / FIN;
    const int E = in_sizes[13];

    float* h_ptr = nullptr;
    __nv_bfloat16 *xhi, *xlo, *ahi, *alo, *whi, *wlo;
    cudaGetSymbolAddress((void**)&h_ptr, g_h);
    cudaGetSymbolAddress((void**)&xhi, g_xhi);
    cudaGetSymbolAddress((void**)&xlo, g_xlo);
    cudaGetSymbolAddress((void**)&ahi, g_ahi);
    cudaGetSymbolAddress((void**)&alo, g_alo);
    cudaGetSymbolAddress((void**)&whi, g_wthi);
    cudaGetSymbolAddress((void**)&wlo, g_wtlo);

    // smem: 4 tile arrays of 128*SW words
    const int SW80  = KIN / 2 + 4;   // 44
    const int SW128 = HDIM / 2 + 4;  // 68
    const size_t shm80  = (size_t)(4 * 128 * SW80) * 4;    // ~90 KB
    const size_t shm128 = (size_t)(4 * 128 * SW128) * 4;   // ~139 KB
    cudaFuncSetAttribute(k_gemm_tc<KIN>,  cudaFuncAttributeMaxDynamicSharedMemorySize, (int)shm80);
    cudaFuncSetAttribute(k_gemm_tc<HDIM>, cudaFuncAttributeMaxDynamicSharedMemorySize, (int)shm128);

    // prep first (independent), then CSR chain: order chosen so the ncu
    // window (-s 5 -c 1) lands on a heavy kernel (gemm/scan) next capture.
    int prepTot = N * KIN + 128 * KIN + 3 * 128 * 128;
    k_prep<<<(prepTot + 255) / 256, 256>>>(x, W_in, W_g0, W_g1, W_g2, N);

    int initMax = (N > NG * HDIM) ? N : NG * HDIM;
    k_init<<<(initMax + 255) / 256, 256>>>(N);
    k_hist<<<(E + 255) / 256, 256>>>(src, dst, E);
    k_scan<<<1, 1024>>>(N);
    k_fill<<<(E + 255) / 256, 256>>>(src, dst, E);

    int gemm_blocks = (N + 127) / 128;
    // embedding_in: h = silu(x @ W_in + b_in)
    k_gemm_tc<KIN><<<gemm_blocks, 256, shm80>>>(xhi, xlo,
        whi + WT_IN_OFF, wlo + WT_IN_OFF, b_in, h_ptr, N);

    const float* bg[3] = {b_g0, b_g1, b_g2};
    int agg_blocks = (N * 32 + 255) / 256;
    for (int l = 0; l < 3; ++l) {
        k_agg<<<agg_blocks, 256>>>(h_ptr, N);
        k_gemm_tc<HDIM><<<gemm_blocks, 256, shm128>>>(ahi, alo,
            whi + WT_G_OFF + l * 128 * 128, wlo + WT_G_OFF + l * 128 * 128,
            bg[l], h_ptr, N);
    }

    k_pool<<<(N + 127) / 128, 128>>>(h_ptr, gids, N);
    k_final<<<NG, HDIM>>>(W_out, b_out, W_ff, b_ff, out);
}

// round 8
// speedup vs baseline: 1.0008x; 1.0008x over previous
#include <cuda_runtime.h>
#include <cuda_bf16.h>
#include <math.h>

// Problem constants
#define NMAX   50000
#define EMAX   600000
#define FIN    74
#define KIN    80          // FIN padded to multiple of 16
#define HDIM   128
#define NG     500

// ---------------- scratch (device globals) ----------------
__device__ __align__(16) float g_h[NMAX * HDIM];            // node features fp32
__device__ __align__(16) __nv_bfloat16 g_ahi[NMAX * HDIM];  // GEMM A operand hi
__device__ __align__(16) __nv_bfloat16 g_alo[NMAX * HDIM];  // GEMM A operand lo
__device__ __align__(16) __nv_bfloat16 g_xhi[NMAX * KIN];   // padded x hi
__device__ __align__(16) __nv_bfloat16 g_xlo[NMAX * KIN];   // padded x lo
// transposed weights: Wt[n][k].  in: 128*80, g0/g1/g2: 128*128 each
#define WT_IN_OFF  0
#define WT_G_OFF   (128*KIN)
#define WT_TOTAL   (128*KIN + 3*128*128)
__device__ __align__(16) __nv_bfloat16 g_wthi[WT_TOTAL];
__device__ __align__(16) __nv_bfloat16 g_wtlo[WT_TOTAL];

__device__ int   g_outcnt[NMAX];
__device__ int   g_incnt[NMAX];
__device__ int   g_rowptr[NMAX + 1];
__device__ int   g_fill[NMAX];
__device__ int   g_col[EMAX];
__device__ float g_outnorm[NMAX];
__device__ float g_innorm[NMAX];
__device__ __align__(16) float g_pooled[NG * HDIM];
__device__ int   g_gcnt[NG];

// ---------------- init ----------------
__global__ void k_init(int N) {
    int i = blockIdx.x * blockDim.x + threadIdx.x;
    if (i < N) { g_outcnt[i] = 0; g_incnt[i] = 0; }
    if (i < NG * HDIM) g_pooled[i] = 0.0f;
    if (i < NG) g_gcnt[i] = 0;
}

// ---------------- degree histogram ----------------
__global__ void k_hist(const int* __restrict__ src, const int* __restrict__ dst, int E) {
    int i = blockIdx.x * blockDim.x + threadIdx.x;
    if (i < E) {
        atomicAdd(&g_outcnt[src[i]], 1);
        atomicAdd(&g_incnt[dst[i]], 1);
    }
}

// ---------------- single-block scan: rowptr + norms ----------------
__global__ void k_scan(int N) {
    __shared__ int sh[1024];
    int t = threadIdx.x;
    int CH = (N + 1023) >> 10;
    int a0 = t * CH;
    int a1 = a0 + CH; if (a1 > N) a1 = N;
    int s = 0;
    for (int i = a0; i < a1; ++i) s += g_incnt[i];
    sh[t] = s;
    __syncthreads();
    for (int off = 1; off < 1024; off <<= 1) {
        int v = (t >= off) ? sh[t - off] : 0;
        __syncthreads();
        sh[t] += v;
        __syncthreads();
    }
    int base = sh[t] - s;
    for (int i = a0; i < a1; ++i) {
        int c = g_incnt[i];
        g_rowptr[i] = base;
        g_fill[i]   = base;
        base += c;
        g_innorm[i]  = rsqrtf((float)(c > 0 ? c : 1));
        int oc = g_outcnt[i];
        g_outnorm[i] = rsqrtf((float)(oc > 0 ? oc : 1));
    }
    if (t == 1023) g_rowptr[N] = sh[1023];
}

// ---------------- CSR placement ----------------
__global__ void k_fill(const int* __restrict__ src, const int* __restrict__ dst, int E) {
    int i = blockIdx.x * blockDim.x + threadIdx.x;
    if (i < E) {
        int d = dst[i];
        int p = atomicAdd(&g_fill[d], 1);
        g_col[p] = src[i];
    }
}

// ---------------- hi/lo split helpers ----------------
__device__ __forceinline__ void split_bf(float v, __nv_bfloat16& hi, __nv_bfloat16& lo) {
    hi = __float2bfloat16_rn(v);
    lo = __float2bfloat16_rn(v - __bfloat162float(hi));
}

// ---------------- fused prep: pad+split x, transpose+split weights ---------
__global__ void k_prep(const float* __restrict__ x,
                       const float* __restrict__ Win,
                       const float* __restrict__ Wg0,
                       const float* __restrict__ Wg1,
                       const float* __restrict__ Wg2, int N) {
    int i = blockIdx.x * blockDim.x + threadIdx.x;
    int nx = N * KIN;
    if (i < nx) {
        int r = i / KIN, k = i - r * KIN;
        float v = (k < FIN) ? x[r * FIN + k] : 0.0f;
        split_bf(v, g_xhi[i], g_xlo[i]);
        return;
    }
    i -= nx;
    if (i < 128 * KIN) {
        int n = i / KIN, k = i % KIN;
        float v = (k < FIN) ? Win[k * 128 + n] : 0.0f;
        split_bf(v, g_wthi[WT_IN_OFF + i], g_wtlo[WT_IN_OFF + i]);
    } else if (i < 128 * KIN + 3 * 128 * 128) {
        int j = i - 128 * KIN;
        int l = j / (128 * 128);
        int r = j - l * 128 * 128;
        int n = r / 128, k = r % 128;
        const float* W = (l == 0) ? Wg0 : (l == 1) ? Wg1 : Wg2;
        float v = W[k * 128 + n];
        split_bf(v, g_wthi[WT_G_OFF + j], g_wtlo[WT_G_OFF + j]);
    }
}

// ---------------- tensor-core GEMM + bias + SiLU ----------------
// out[N,128] = silu(A[N,KP] @ W[KP,128] + b), A/W split hi+lo bf16.
// Block: 256 thr (8 warps = 4M x 2N), tile 128 rows x 128 cols.
// Warp tile: 32 rows (two m16) x 64 cols (eight n8).
__device__ __forceinline__ float silu1(float v) { return v / (1.0f + __expf(-v)); }

__device__ __forceinline__ void mma16816(float* d, const unsigned* a, const unsigned* b) {
    asm volatile(
        "mma.sync.aligned.m16n8k16.row.col.f32.bf16.bf16.f32 "
        "{%0,%1,%2,%3}, {%4,%5,%6,%7}, {%8,%9}, {%0,%1,%2,%3};"
        : "+f"(d[0]), "+f"(d[1]), "+f"(d[2]), "+f"(d[3])
        : "r"(a[0]), "r"(a[1]), "r"(a[2]), "r"(a[3]), "r"(b[0]), "r"(b[1]));
}

__device__ __forceinline__ void ldsm4(unsigned* r, unsigned addr) {
    asm volatile("ldmatrix.sync.aligned.m8n8.x4.shared.b16 {%0,%1,%2,%3}, [%4];"
                 : "=r"(r[0]), "=r"(r[1]), "=r"(r[2]), "=r"(r[3]) : "r"(addr));
}

template <int KP>
__global__ void __launch_bounds__(256)
k_gemm_tc(const __nv_bfloat16* __restrict__ Ahi, const __nv_bfloat16* __restrict__ Alo,
          const __nv_bfloat16* __restrict__ Whi, const __nv_bfloat16* __restrict__ Wlo,
          const float* __restrict__ bias, float* __restrict__ out, int N) {
    constexpr int SW = KP / 2 + 4;             // padded row stride in 32-bit words
    constexpr int TW = 128 * SW;               // words per tile array
    extern __shared__ unsigned sh[];
    unsigned* sAh = sh;
    unsigned* sAl = sh + TW;
    unsigned* sWh = sh + 2 * TW;
    unsigned* sWl = sh + 3 * TW;

    const int tid  = threadIdx.x;
    const int lane = tid & 31;
    const int gid  = lane >> 2;
    const int tig  = lane & 3;
    const int warp = tid >> 5;
    const int wm   = warp & 3;        // M group (32 rows each)
    const int wn   = warp >> 2;       // N group (64 cols each)
    const int r0   = blockIdx.x * 128;

    // stage tiles: uint4 = 8 bf16 = 4 words
    constexpr int ACH = KP / 8;       // uint4 chunks per row
    for (int i = tid; i < 128 * ACH; i += 256) {
        int r = i / ACH, c = i - r * ACH;
        int gr = r0 + r;
        uint4 vh = make_uint4(0, 0, 0, 0), vl = vh;
        if (gr < N) {
            vh = reinterpret_cast<const uint4*>(Ahi + (size_t)gr * KP)[c];
            vl = reinterpret_cast<const uint4*>(Alo + (size_t)gr * KP)[c];
        }
        *reinterpret_cast<uint4*>(sAh + r * SW + c * 4) = vh;
        *reinterpret_cast<uint4*>(sAl + r * SW + c * 4) = vl;
        *reinterpret_cast<uint4*>(sWh + r * SW + c * 4) =
            reinterpret_cast<const uint4*>(Whi + (size_t)r * KP)[c];
        *reinterpret_cast<uint4*>(sWl + r * SW + c * 4) =
            reinterpret_cast<const uint4*>(Wlo + (size_t)r * KP)[c];
    }
    __syncthreads();

    // shared-space byte addresses for ldmatrix
    unsigned base_sh = (unsigned)__cvta_generic_to_shared(sh);
    // A: lane 0-15 -> rows m0..m0+15; lane>=16 -> +16B column offset
    int rowA = wm * 32 + (lane & 15);
    unsigned aoff = (unsigned)(rowA * SW) * 4u + ((lane >> 4) * 16u);
    // B: lanes {0-7,8-15,16-23,24-31} -> (n 0-7 k0),(n 0-7 k8),(n 8-15 k0),(n 8-15 k8)
    int rowB = wn * 64 + ((lane >> 4) << 3) + (lane & 7);
    unsigned boff = (unsigned)(rowB * SW) * 4u + (((lane >> 3) & 1) * 16u);

    unsigned aAh = base_sh + aoff;                    // into sAh
    unsigned aAl = base_sh + 4u * TW + aoff;          // into sAl (word offset TW)
    unsigned aWh = base_sh + 8u * TW + boff;
    unsigned aWl = base_sh + 12u * TW + boff;

    // accumulators: [mi][nt][4], init with bias
    float d[2][8][4];
#pragma unroll
    for (int nt = 0; nt < 8; ++nt) {
        int c = wn * 64 + nt * 8 + tig * 2;
        float b0 = bias[c], b1 = bias[c + 1];
#pragma unroll
        for (int mi = 0; mi < 2; ++mi) {
            d[mi][nt][0] = b0; d[mi][nt][1] = b1;
            d[mi][nt][2] = b0; d[mi][nt][3] = b1;
        }
    }

#pragma unroll
    for (int ks = 0; ks < KP / 16; ++ks) {
        unsigned kb = ks * 32u;  // 16 bf16 = 32 bytes
        unsigned ah[2][4], al[2][4];
#pragma unroll
        for (int mi = 0; mi < 2; ++mi) {
            unsigned mo = (unsigned)(mi * 16 * SW) * 4u + kb;
            ldsm4(ah[mi], aAh + mo);
            ldsm4(al[mi], aAl + mo);
        }
        unsigned bh[4][4], bl[4][4];
#pragma unroll
        for (int np = 0; np < 4; ++np) {
            unsigned no = (unsigned)(np * 16 * SW) * 4u + kb;
            ldsm4(bh[np], aWh + no);
            ldsm4(bl[np], aWl + no);
        }
#pragma unroll
        for (int nt = 0; nt < 8; ++nt) {
            const unsigned* bhp = &bh[nt >> 1][(nt & 1) * 2];
            const unsigned* blp = &bl[nt >> 1][(nt & 1) * 2];
#pragma unroll
            for (int mi = 0; mi < 2; ++mi) {
                mma16816(d[mi][nt], ah[mi], bhp);
                mma16816(d[mi][nt], ah[mi], blp);
                mma16816(d[mi][nt], al[mi], bhp);
            }
        }
    }

    // epilogue: silu + store fp32
#pragma unroll
    for (int mi = 0; mi < 2; ++mi) {
        int r1 = r0 + wm * 32 + mi * 16 + gid;
        int r2 = r1 + 8;
#pragma unroll
        for (int nt = 0; nt < 8; ++nt) {
            int c = wn * 64 + nt * 8 + tig * 2;
            if (r1 < N) {
                float2 v = make_float2(silu1(d[mi][nt][0]), silu1(d[mi][nt][1]));
                *reinterpret_cast<float2*>(out + (size_t)r1 * 128 + c) = v;
            }
            if (r2 < N) {
                float2 v = make_float2(silu1(d[mi][nt][2]), silu1(d[mi][nt][3]));
                *reinterpret_cast<float2*>(out + (size_t)r2 * 128 + c) = v;
            }
        }
    }
}

// ---------------- gather-aggregate -> bf16 hi/lo output ----------------
__global__ void k_agg(const float* __restrict__ h, int N) {
    int w = (blockIdx.x * blockDim.x + threadIdx.x) >> 5;
    int lane = threadIdx.x & 31;
    if (w >= N) return;
    int e0 = g_rowptr[w], e1 = g_rowptr[w + 1];
    const float4* h4 = reinterpret_cast<const float4*>(h);
    float4 acc = make_float4(0.f, 0.f, 0.f, 0.f);
    for (int e = e0; e < e1; ++e) {
        int s = g_col[e];
        float on = g_outnorm[s];
        float4 v = h4[s * 32 + lane];
        acc.x = fmaf(on, v.x, acc.x);
        acc.y = fmaf(on, v.y, acc.y);
        acc.z = fmaf(on, v.z, acc.z);
        acc.w = fmaf(on, v.w, acc.w);
    }
    float inn = g_innorm[w];
    float o[4] = {acc.x * inn, acc.y * inn, acc.z * inn, acc.w * inn};
    __nv_bfloat16 hi[4], lo[4];
#pragma unroll
    for (int j = 0; j < 4; ++j) split_bf(o[j], hi[j], lo[j]);
    size_t base = (size_t)w * 128 + lane * 4;
    *reinterpret_cast<__nv_bfloat162*>(g_ahi + base)     = __nv_bfloat162(hi[0], hi[1]);
    *reinterpret_cast<__nv_bfloat162*>(g_ahi + base + 2) = __nv_bfloat162(hi[2], hi[3]);
    *reinterpret_cast<__nv_bfloat162*>(g_alo + base)     = __nv_bfloat162(lo[0], lo[1]);
    *reinterpret_cast<__nv_bfloat162*>(g_alo + base + 2) = __nv_bfloat162(lo[2], lo[3]);
}

// ---------------- segment-sum pooling (graph_ids sorted) ----------------
__global__ void k_pool(const float* __restrict__ h, const int* __restrict__ gid, int N) {
    int r0 = blockIdx.x * 128;
    if (r0 >= N) return;
    int r1 = r0 + 128; if (r1 > N) r1 = N;
    int j = threadIdx.x;
    int cur = gid[r0];
    float acc = 0.0f;
    int run = 0;
    for (int r = r0; r < r1; ++r) {
        int g = gid[r];
        if (g != cur) {
            atomicAdd(&g_pooled[cur * HDIM + j], acc);
            if (j == 0) atomicAdd(&g_gcnt[cur], run);
            acc = 0.0f; run = 0; cur = g;
        }
        acc += h[(size_t)r * HDIM + j];
        ++run;
    }
    atomicAdd(&g_pooled[cur * HDIM + j], acc);
    if (j == 0) atomicAdd(&g_gcnt[cur], run);
}

// ---------------- final: (pooled @ W_out + cnt*b_out) @ W_ff + b_ff ----------
__global__ void k_final(const float* __restrict__ Wout, const float* __restrict__ bout,
                        const float* __restrict__ Wff, const float* __restrict__ bff,
                        float* __restrict__ out) {
    __shared__ float p[HDIM];
    __shared__ float red[HDIM];
    int g = blockIdx.x, j = threadIdx.x;
    p[j] = g_pooled[g * HDIM + j];
    __syncthreads();
    float t = (float)g_gcnt[g] * bout[j];
#pragma unroll 8
    for (int k = 0; k < HDIM; ++k)
        t = fmaf(p[k], Wout[k * HDIM + j], t);
    red[j] = t * Wff[j];
    __syncthreads();
    for (int s = 64; s > 0; s >>= 1) {
        if (j < s) red[j] += red[j + s];
        __syncthreads();
    }
    if (j == 0) out[g] = red[0] + bff[0];
}

// ---------------- launch ----------------
extern "C" void kernel_launch(void* const* d_in, const int* in_sizes, int n_in,
                              void* d_out, int out_size) {
    const float* x     = (const float*)d_in[0];
    const float* W_in  = (const float*)d_in[1];
    const float* b_in  = (const float*)d_in[2];
    const float* W_g0  = (const float*)d_in[3];
    const float* b_g0  = (const float*)d_in[4];
    const float* W_g1  = (const float*)d_in[5];
    const float* b_g1  = (const float*)d_in[6];
    const float* W_g2  = (const float*)d_in[7];
    const float* b_g2  = (const float*)d_in[8];
    const float* W_out = (const float*)d_in[9];
    const float* b_out = (const float*)d_in[10];
    const float* W_ff  = (const float*)d_in[11];
    const float* b_ff  = (const float*)d_in[12];
    const int*   src   = (const int*)d_in[13];
    const int*   dst   = (const int*)d_in[14];
    const int*   gids  = (const int*)d_in[15];
    float* out = (float*)d_out;

    const int N = in_sizes[0] / FIN;
    const int E = in_sizes[13];

    float* h_ptr = nullptr;
    __nv_bfloat16 *xhi, *xlo, *ahi, *alo, *whi, *wlo;
    cudaGetSymbolAddress((void**)&h_ptr, g_h);
    cudaGetSymbolAddress((void**)&xhi, g_xhi);
    cudaGetSymbolAddress((void**)&xlo, g_xlo);
    cudaGetSymbolAddress((void**)&ahi, g_ahi);
    cudaGetSymbolAddress((void**)&alo, g_alo);
    cudaGetSymbolAddress((void**)&whi, g_wthi);
    cudaGetSymbolAddress((void**)&wlo, g_wtlo);

    // smem: 4 tile arrays of 128*SW words
    const int SW80  = KIN / 2 + 4;   // 44
    const int SW128 = HDIM / 2 + 4;  // 68
    const size_t shm80  = (size_t)(4 * 128 * SW80) * 4;    // ~90 KB
    const size_t shm128 = (size_t)(4 * 128 * SW128) * 4;   // ~139 KB
    cudaFuncSetAttribute(k_gemm_tc<KIN>,  cudaFuncAttributeMaxDynamicSharedMemorySize, (int)shm80);
    cudaFuncSetAttribute(k_gemm_tc<HDIM>, cudaFuncAttributeMaxDynamicSharedMemorySize, (int)shm128);

    // prep first (independent), then CSR chain: order chosen so the ncu
    // window (-s 5 -c 1) lands on a heavy kernel (gemm/scan) next capture.
    int prepTot = N * KIN + 128 * KIN + 3 * 128 * 128;
    k_prep<<<(prepTot + 255) / 256, 256>>>(x, W_in, W_g0, W_g1, W_g2, N);

    int initMax = (N > NG * HDIM) ? N : NG * HDIM;
    k_init<<<(initMax + 255) / 256, 256>>>(N);
    k_hist<<<(E + 255) / 256, 256>>>(src, dst, E);
    k_scan<<<1, 1024>>>(N);
    k_fill<<<(E + 255) / 256, 256>>>(src, dst, E);

    int gemm_blocks = (N + 127) / 128;
    // embedding_in: h = silu(x @ W_in + b_in)
    k_gemm_tc<KIN><<<gemm_blocks, 256, shm80>>>(xhi, xlo,
        whi + WT_IN_OFF, wlo + WT_IN_OFF, b_in, h_ptr, N);

    const float* bg[3] = {b_g0, b_g1, b_g2};
    int agg_blocks = (N * 32 + 255) / 256;
    for (int l = 0; l < 3; ++l) {
        k_agg<<<agg_blocks, 256>>>(h_ptr, N);
        k_gemm_tc<HDIM><<<gemm_blocks, 256, shm128>>>(ahi, alo,
            whi + WT_G_OFF + l * 128 * 128, wlo + WT_G_OFF + l * 128 * 128,
            bg[l], h_ptr, N);
    }

    k_pool<<<(N + 127) / 128, 128>>>(h_ptr, gids, N);
    k_final<<<NG, HDIM>>>(W_out, b_out, W_ff, b_ff, out);
}

// round 9
// speedup vs baseline: 1.6991x; 1.6978x over previous
#include <cuda_runtime.h>
#include <cuda_bf16.h>
#include <math.h>

// Problem constants
#define NMAX   50000
#define EMAX   600000
#define FIN    74
#define KIN    80          // FIN padded to multiple of 16
#define HDIM   128
#define NG     500
#define SCHUNK 1024        // nodes per scan block
#define NBMAX  64

// ---------------- scratch (device globals) ----------------
__device__ __align__(16) float g_h[NMAX * HDIM];            // node features fp32
__device__ __align__(16) __nv_bfloat16 g_ahi[NMAX * HDIM];  // GEMM A operand hi
__device__ __align__(16) __nv_bfloat16 g_alo[NMAX * HDIM];  // GEMM A operand lo
__device__ __align__(16) __nv_bfloat16 g_xhi[NMAX * KIN];   // padded x hi
__device__ __align__(16) __nv_bfloat16 g_xlo[NMAX * KIN];   // padded x lo
// transposed weights: Wt[n][k].  in: 128*80, g0/g1/g2: 128*128 each
#define WT_IN_OFF  0
#define WT_G_OFF   (128*KIN)
#define WT_TOTAL   (128*KIN + 3*128*128)
__device__ __align__(16) __nv_bfloat16 g_wthi[WT_TOTAL];
__device__ __align__(16) __nv_bfloat16 g_wtlo[WT_TOTAL];

__device__ int   g_outcnt[NMAX];
__device__ int   g_incnt[NMAX];
__device__ int   g_rowptr[NMAX + 1];
__device__ int   g_fill[NMAX];
__device__ int   g_col[EMAX];
__device__ float g_outnorm[NMAX];
__device__ float g_innorm[NMAX];
__device__ __align__(16) float g_pooled[NG * HDIM];
__device__ int   g_gcnt[NG];
__device__ int   g_bsum[NBMAX];
__device__ int   g_boff[NBMAX];

// ---------------- init ----------------
__global__ void k_init(int N) {
    int i = blockIdx.x * blockDim.x + threadIdx.x;
    if (i < N) { g_outcnt[i] = 0; g_incnt[i] = 0; }
    if (i < NG * HDIM) g_pooled[i] = 0.0f;
    if (i < NG) g_gcnt[i] = 0;
}

// ---------------- degree histogram ----------------
__global__ void k_hist(const int* __restrict__ src, const int* __restrict__ dst, int E) {
    int i = blockIdx.x * blockDim.x + threadIdx.x;
    if (i < E) {
        atomicAdd(&g_outcnt[src[i]], 1);
        atomicAdd(&g_incnt[dst[i]], 1);
    }
}

// ---------------- parallel scan, phase 1: per-block reduce + norms ----------
__global__ void __launch_bounds__(256) k_scan1(int N) {
    int b = blockIdx.x, t = threadIdx.x;
    int i0 = b * SCHUNK + t * 4;
    int s = 0;
#pragma unroll
    for (int j = 0; j < 4; ++j) {
        int i = i0 + j;
        if (i < N) {
            int c = g_incnt[i];
            s += c;
            g_innorm[i] = rsqrtf((float)(c > 0 ? c : 1));
            int oc = g_outcnt[i];
            g_outnorm[i] = rsqrtf((float)(oc > 0 ? oc : 1));
        }
    }
    __shared__ int red[8];
#pragma unroll
    for (int o = 16; o; o >>= 1) s += __shfl_down_sync(~0u, s, o);
    if ((t & 31) == 0) red[t >> 5] = s;
    __syncthreads();
    if (t < 8) {
        int v = red[t];
#pragma unroll
        for (int o = 4; o; o >>= 1) v += __shfl_down_sync(0xffu, v, o);
        if (t == 0) g_bsum[b] = v;
    }
}

// ---------------- scan phase 2: scan block sums (tiny) ----------------
__global__ void k_scan2(int NB, int N) {
    int t = threadIdx.x;  // 64 threads
    int v = (t < NB) ? g_bsum[t] : 0;
    __shared__ int sh[64];
    sh[t] = v;
    __syncthreads();
    for (int o = 1; o < 64; o <<= 1) {
        int u = (t >= o) ? sh[t - o] : 0;
        __syncthreads();
        sh[t] += u;
        __syncthreads();
    }
    if (t < NB) g_boff[t] = sh[t] - v;  // exclusive
    if (t == 63) g_rowptr[N] = sh[63];
}

// ---------------- scan phase 3: per-block rescan, write rowptr/fill --------
__global__ void __launch_bounds__(256) k_scan3(int N) {
    int b = blockIdx.x, t = threadIdx.x;
    int lane = t & 31, w = t >> 5;
    int i0 = b * SCHUNK + t * 4;
    int c[4];
    int s = 0;
#pragma unroll
    for (int j = 0; j < 4; ++j) {
        int i = i0 + j;
        c[j] = (i < N) ? g_incnt[i] : 0;
        s += c[j];
    }
    // inclusive warp scan of thread sums
    int pre = s;
#pragma unroll
    for (int o = 1; o < 32; o <<= 1) {
        int u = __shfl_up_sync(~0u, pre, o);
        if (lane >= o) pre += u;
    }
    __shared__ int wsum[8];
    if (lane == 31) wsum[w] = pre;
    __syncthreads();
    if (t < 8) {
        int v = wsum[t];
#pragma unroll
        for (int o = 1; o < 8; o <<= 1) {
            int u = __shfl_up_sync(0xffu, v, o);
            if ((int)t >= o) v += u;
        }
        wsum[t] = v;
    }
    __syncthreads();
    int base = g_boff[b] + (w ? wsum[w - 1] : 0) + (pre - s);
#pragma unroll
    for (int j = 0; j < 4; ++j) {
        int i = i0 + j;
        if (i < N) {
            g_rowptr[i] = base;
            g_fill[i]   = base;
            base += c[j];
        }
    }
}

// ---------------- CSR placement ----------------
__global__ void k_fill(const int* __restrict__ src, const int* __restrict__ dst, int E) {
    int i = blockIdx.x * blockDim.x + threadIdx.x;
    if (i < E) {
        int d = dst[i];
        int p = atomicAdd(&g_fill[d], 1);
        g_col[p] = src[i];
    }
}

// ---------------- hi/lo split helpers ----------------
__device__ __forceinline__ void split_bf(float v, __nv_bfloat16& hi, __nv_bfloat16& lo) {
    hi = __float2bfloat16_rn(v);
    lo = __float2bfloat16_rn(v - __bfloat162float(hi));
}

// ---------------- fused prep: pad+split x, transpose+split weights ---------
__global__ void k_prep(const float* __restrict__ x,
                       const float* __restrict__ Win,
                       const float* __restrict__ Wg0,
                       const float* __restrict__ Wg1,
                       const float* __restrict__ Wg2, int N) {
    int i = blockIdx.x * blockDim.x + threadIdx.x;
    int nx = N * KIN;
    if (i < nx) {
        int r = i / KIN, k = i - r * KIN;
        float v = (k < FIN) ? x[r * FIN + k] : 0.0f;
        split_bf(v, g_xhi[i], g_xlo[i]);
        return;
    }
    i -= nx;
    if (i < 128 * KIN) {
        int n = i / KIN, k = i % KIN;
        float v = (k < FIN) ? Win[k * 128 + n] : 0.0f;
        split_bf(v, g_wthi[WT_IN_OFF + i], g_wtlo[WT_IN_OFF + i]);
    } else if (i < 128 * KIN + 3 * 128 * 128) {
        int j = i - 128 * KIN;
        int l = j / (128 * 128);
        int r = j - l * 128 * 128;
        int n = r / 128, k = r % 128;
        const float* W = (l == 0) ? Wg0 : (l == 1) ? Wg1 : Wg2;
        float v = W[k * 128 + n];
        split_bf(v, g_wthi[WT_G_OFF + j], g_wtlo[WT_G_OFF + j]);
    }
}

// ---------------- tensor-core GEMM + bias + SiLU (R6 config) ----------------
// out[N,128] = silu(A[N,KP] @ W[KP,128] + b), A/W split hi+lo bf16.
// Block: 256 thr (8 warps = 2M x 4N), tile 64 rows x 128 cols.
__device__ __forceinline__ float silu1(float v) { return v / (1.0f + __expf(-v)); }

__device__ __forceinline__ void mma16816(float* d, const unsigned* a, const unsigned* b) {
    asm volatile(
        "mma.sync.aligned.m16n8k16.row.col.f32.bf16.bf16.f32 "
        "{%0,%1,%2,%3}, {%4,%5,%6,%7}, {%8,%9}, {%0,%1,%2,%3};"
        : "+f"(d[0]), "+f"(d[1]), "+f"(d[2]), "+f"(d[3])
        : "r"(a[0]), "r"(a[1]), "r"(a[2]), "r"(a[3]), "r"(b[0]), "r"(b[1]));
}

template <int KP>
__global__ void __launch_bounds__(256)
k_gemm_tc(const __nv_bfloat16* __restrict__ Ahi, const __nv_bfloat16* __restrict__ Alo,
          const __nv_bfloat16* __restrict__ Whi, const __nv_bfloat16* __restrict__ Wlo,
          const float* __restrict__ bias, float* __restrict__ out, int N) {
    constexpr int SW = KP / 2 + 4;             // padded stride in 32-bit words
    constexpr int AW = 64 * SW;                // words per A array
    constexpr int WW = 128 * SW;               // words per W array
    extern __shared__ unsigned sh[];
    unsigned* sAh = sh;
    unsigned* sAl = sh + AW;
    unsigned* sWh = sh + 2 * AW;
    unsigned* sWl = sh + 2 * AW + WW;

    const int tid  = threadIdx.x;
    const int lane = tid & 31;
    const int gid  = lane >> 2;
    const int tig  = lane & 3;
    const int warp = tid >> 5;
    const int wm   = warp & 1;        // M group (32 rows)
    const int wn   = warp >> 1;       // N group (32 cols)
    const int r0   = blockIdx.x * 64;

    constexpr int ACH = KP / 8;       // uint4 chunks per row
    for (int i = tid; i < 64 * ACH; i += 256) {
        int r = i / ACH, c = i - r * ACH;
        int gr = r0 + r;
        uint4 vh = make_uint4(0, 0, 0, 0), vl = vh;
        if (gr < N) {
            vh = reinterpret_cast<const uint4*>(Ahi + (size_t)gr * KP)[c];
            vl = reinterpret_cast<const uint4*>(Alo + (size_t)gr * KP)[c];
        }
        *reinterpret_cast<uint4*>(sAh + r * SW + c * 4) = vh;
        *reinterpret_cast<uint4*>(sAl + r * SW + c * 4) = vl;
    }
    for (int i = tid; i < 128 * ACH; i += 256) {
        int n = i / ACH, c = i - n * ACH;
        *reinterpret_cast<uint4*>(sWh + n * SW + c * 4) =
            reinterpret_cast<const uint4*>(Whi + (size_t)n * KP)[c];
        *reinterpret_cast<uint4*>(sWl + n * SW + c * 4) =
            reinterpret_cast<const uint4*>(Wlo + (size_t)n * KP)[c];
    }
    __syncthreads();

    float d[2][4][4];
#pragma unroll
    for (int nt = 0; nt < 4; ++nt) {
        int c = wn * 32 + nt * 8 + tig * 2;
        float b0 = bias[c], b1 = bias[c + 1];
#pragma unroll
        for (int mi = 0; mi < 2; ++mi) {
            d[mi][nt][0] = b0; d[mi][nt][1] = b1;
            d[mi][nt][2] = b0; d[mi][nt][3] = b1;
        }
    }

#pragma unroll
    for (int ks = 0; ks < KP / 16; ++ks) {
        unsigned ah[2][4], al[2][4];
#pragma unroll
        for (int mi = 0; mi < 2; ++mi) {
            int rr = wm * 32 + mi * 16 + gid;
            int base = ks * 8 + tig;
            ah[mi][0] = sAh[rr * SW + base];
            ah[mi][1] = sAh[(rr + 8) * SW + base];
            ah[mi][2] = sAh[rr * SW + base + 4];
            ah[mi][3] = sAh[(rr + 8) * SW + base + 4];
            al[mi][0] = sAl[rr * SW + base];
            al[mi][1] = sAl[(rr + 8) * SW + base];
            al[mi][2] = sAl[rr * SW + base + 4];
            al[mi][3] = sAl[(rr + 8) * SW + base + 4];
        }
#pragma unroll
        for (int nt = 0; nt < 4; ++nt) {
            int n = wn * 32 + nt * 8 + gid;
            int base = n * SW + ks * 8 + tig;
            unsigned bh[2], bl[2];
            bh[0] = sWh[base]; bh[1] = sWh[base + 4];
            bl[0] = sWl[base]; bl[1] = sWl[base + 4];
#pragma unroll
            for (int mi = 0; mi < 2; ++mi) {
                mma16816(d[mi][nt], ah[mi], bh);
                mma16816(d[mi][nt], ah[mi], bl);
                mma16816(d[mi][nt], al[mi], bh);
            }
        }
    }

#pragma unroll
    for (int mi = 0; mi < 2; ++mi) {
        int r1 = r0 + wm * 32 + mi * 16 + gid;
        int r2 = r1 + 8;
#pragma unroll
        for (int nt = 0; nt < 4; ++nt) {
            int c = wn * 32 + nt * 8 + tig * 2;
            if (r1 < N) {
                float2 v = make_float2(silu1(d[mi][nt][0]), silu1(d[mi][nt][1]));
                *reinterpret_cast<float2*>(out + (size_t)r1 * 128 + c) = v;
            }
            if (r2 < N) {
                float2 v = make_float2(silu1(d[mi][nt][2]), silu1(d[mi][nt][3]));
                *reinterpret_cast<float2*>(out + (size_t)r2 * 128 + c) = v;
            }
        }
    }
}

// ---------------- gather-aggregate -> bf16 hi/lo output ----------------
__global__ void k_agg(const float* __restrict__ h, int N) {
    int w = (blockIdx.x * blockDim.x + threadIdx.x) >> 5;
    int lane = threadIdx.x & 31;
    if (w >= N) return;
    int e0 = g_rowptr[w], e1 = g_rowptr[w + 1];
    const float4* h4 = reinterpret_cast<const float4*>(h);
    float4 acc = make_float4(0.f, 0.f, 0.f, 0.f);
    for (int e = e0; e < e1; ++e) {
        int s = g_col[e];
        float on = g_outnorm[s];
        float4 v = h4[s * 32 + lane];
        acc.x = fmaf(on, v.x, acc.x);
        acc.y = fmaf(on, v.y, acc.y);
        acc.z = fmaf(on, v.z, acc.z);
        acc.w = fmaf(on, v.w, acc.w);
    }
    float inn = g_innorm[w];
    float o[4] = {acc.x * inn, acc.y * inn, acc.z * inn, acc.w * inn};
    __nv_bfloat16 hi[4], lo[4];
#pragma unroll
    for (int j = 0; j < 4; ++j) split_bf(o[j], hi[j], lo[j]);
    size_t base = (size_t)w * 128 + lane * 4;
    *reinterpret_cast<__nv_bfloat162*>(g_ahi + base)     = __nv_bfloat162(hi[0], hi[1]);
    *reinterpret_cast<__nv_bfloat162*>(g_ahi + base + 2) = __nv_bfloat162(hi[2], hi[3]);
    *reinterpret_cast<__nv_bfloat162*>(g_alo + base)     = __nv_bfloat162(lo[0], lo[1]);
    *reinterpret_cast<__nv_bfloat162*>(g_alo + base + 2) = __nv_bfloat162(lo[2], lo[3]);
}

// ---------------- segment-sum pooling (graph_ids sorted) ----------------
__global__ void k_pool(const float* __restrict__ h, const int* __restrict__ gid, int N) {
    int r0 = blockIdx.x * 128;
    if (r0 >= N) return;
    int r1 = r0 + 128; if (r1 > N) r1 = N;
    int j = threadIdx.x;
    int cur = gid[r0];
    float acc = 0.0f;
    int run = 0;
    for (int r = r0; r < r1; ++r) {
        int g = gid[r];
        if (g != cur) {
            atomicAdd(&g_pooled[cur * HDIM + j], acc);
            if (j == 0) atomicAdd(&g_gcnt[cur], run);
            acc = 0.0f; run = 0; cur = g;
        }
        acc += h[(size_t)r * HDIM + j];
        ++run;
    }
    atomicAdd(&g_pooled[cur * HDIM + j], acc);
    if (j == 0) atomicAdd(&g_gcnt[cur], run);
}

// ---------------- final: (pooled @ W_out + cnt*b_out) @ W_ff + b_ff ----------
__global__ void k_final(const float* __restrict__ Wout, const float* __restrict__ bout,
                        const float* __restrict__ Wff, const float* __restrict__ bff,
                        float* __restrict__ out) {
    __shared__ float p[HDIM];
    __shared__ float red[HDIM];
    int g = blockIdx.x, j = threadIdx.x;
    p[j] = g_pooled[g * HDIM + j];
    __syncthreads();
    float t = (float)g_gcnt[g] * bout[j];
#pragma unroll 8
    for (int k = 0; k < HDIM; ++k)
        t = fmaf(p[k], Wout[k * HDIM + j], t);
    red[j] = t * Wff[j];
    __syncthreads();
    for (int s = 64; s > 0; s >>= 1) {
        if (j < s) red[j] += red[j + s];
        __syncthreads();
    }
    if (j == 0) out[g] = red[0] + bff[0];
}

// ---------------- launch ----------------
extern "C" void kernel_launch(void* const* d_in, const int* in_sizes, int n_in,
                              void* d_out, int out_size) {
    const float* x     = (const float*)d_in[0];
    const float* W_in  = (const float*)d_in[1];
    const float* b_in  = (const float*)d_in[2];
    const float* W_g0  = (const float*)d_in[3];
    const float* b_g0  = (const float*)d_in[4];
    const float* W_g1  = (const float*)d_in[5];
    const float* b_g1  = (const float*)d_in[6];
    const float* W_g2  = (const float*)d_in[7];
    const float* b_g2  = (const float*)d_in[8];
    const float* W_out = (const float*)d_in[9];
    const float* b_out = (const float*)d_in[10];
    const float* W_ff  = (const float*)d_in[11];
    const float* b_ff  = (const float*)d_in[12];
    const int*   src   = (const int*)d_in[13];
    const int*   dst   = (const int*)d_in[14];
    const int*   gids  = (const int*)d_in[15];
    float* out = (float*)d_out;

    const int N = in_sizes[0] / FIN;
    const int E = in_sizes[13];
    const int NB = (N + SCHUNK - 1) / SCHUNK;

    float* h_ptr = nullptr;
    __nv_bfloat16 *xhi, *xlo, *ahi, *alo, *whi, *wlo;
    cudaGetSymbolAddress((void**)&h_ptr, g_h);
    cudaGetSymbolAddress((void**)&xhi, g_xhi);
    cudaGetSymbolAddress((void**)&xlo, g_xlo);
    cudaGetSymbolAddress((void**)&ahi, g_ahi);
    cudaGetSymbolAddress((void**)&alo, g_alo);
    cudaGetSymbolAddress((void**)&whi, g_wthi);
    cudaGetSymbolAddress((void**)&wlo, g_wtlo);

    const int SW80  = KIN / 2 + 4;   // 44
    const int SW128 = HDIM / 2 + 4;  // 68
    const size_t shm80  = (size_t)(2 * 64 * SW80 + 2 * 128 * SW80) * 4;    // ~67.5 KB
    const size_t shm128 = (size_t)(2 * 64 * SW128 + 2 * 128 * SW128) * 4;  // ~102 KB
    cudaFuncSetAttribute(k_gemm_tc<KIN>,  cudaFuncAttributeMaxDynamicSharedMemorySize, (int)shm80);
    cudaFuncSetAttribute(k_gemm_tc<HDIM>, cudaFuncAttributeMaxDynamicSharedMemorySize, (int)shm128);

    int initMax = (N > NG * HDIM) ? N : NG * HDIM;
    int prepTot = N * KIN + 128 * KIN + 3 * 128 * 128;
    int gemm_blocks = (N + 63) / 64;

    // Launch order: gemm_in placed at stream index 5 so the ncu window
    // (-s 5 -c 1) profiles a GEMM next round. Deps: gemm_in needs only prep.
    k_prep<<<(prepTot + 255) / 256, 256>>>(x, W_in, W_g0, W_g1, W_g2, N);   // 0
    k_init<<<(initMax + 255) / 256, 256>>>(N);                              // 1
    k_hist<<<(E + 255) / 256, 256>>>(src, dst, E);                          // 2
    k_scan1<<<NB, 256>>>(N);                                                // 3
    k_scan2<<<1, 64>>>(NB, N);                                              // 4
    k_gemm_tc<KIN><<<gemm_blocks, 256, shm80>>>(xhi, xlo,                   // 5
        whi + WT_IN_OFF, wlo + WT_IN_OFF, b_in, h_ptr, N);
    k_scan3<<<NB, 256>>>(N);                                                // 6
    k_fill<<<(E + 255) / 256, 256>>>(src, dst, E);                          // 7

    const float* bg[3] = {b_g0, b_g1, b_g2};
    int agg_blocks = (N * 32 + 255) / 256;
    for (int l = 0; l < 3; ++l) {
        k_agg<<<agg_blocks, 256>>>(h_ptr, N);
        k_gemm_tc<HDIM><<<gemm_blocks, 256, shm128>>>(ahi, alo,
            whi + WT_G_OFF + l * 128 * 128, wlo + WT_G_OFF + l * 128 * 128,
            bg[l], h_ptr, N);
    }

    k_pool<<<(N + 127) / 128, 128>>>(h_ptr, gids, N);
    k_final<<<NG, HDIM>>>(W_out, b_out, W_ff, b_ff, out);
}